// round 1
// baseline (speedup 1.0000x reference)
#include <cuda_runtime.h>

// DynamicRouting: B=128, IN=2048, OUT=32, POSE=4, 3 routing iterations.
// poses_out [B,32,4] followed by activations_out [B,32] in d_out.

#define NB 128
#define NI 2048
#define NO 32
#define NP 4
#define EPSF 1e-7f
#define NWARPS 32
#define NTHREADS (NWARPS * 32)

__device__ __forceinline__ float warpAllMax(float x) {
#pragma unroll
    for (int m = 16; m > 0; m >>= 1)
        x = fmaxf(x, __shfl_xor_sync(0xffffffffu, x, m));
    return x;
}

__device__ __forceinline__ float warpAllSum(float x) {
#pragma unroll
    for (int m = 16; m > 0; m >>= 1)
        x += __shfl_xor_sync(0xffffffffu, x, m);
    return x;
}

__global__ __launch_bounds__(NTHREADS, 1)
void routing_kernel(const float4* __restrict__ votes, float* __restrict__ out) {
    const int b    = blockIdx.x;
    const int tid  = threadIdx.x;
    const int w    = tid >> 5;      // warp id, 0..31
    const int lane = tid & 31;      // lane == output-capsule index o

    __shared__ float4 part4[NWARPS][NO];   // per-warp partial s: 16 KB
    __shared__ float4 vsh4[2][NO];         // v1, v2
    __shared__ float  s_sh[NO * NP];       // reduced s

    const float4* vb = votes + (size_t)b * (NI * NO);

    float4 v1 = make_float4(0.f, 0.f, 0.f, 0.f);
    float4 v2 = make_float4(0.f, 0.f, 0.f, 0.f);

#pragma unroll
    for (int it = 0; it < 3; ++it) {
        float ax = 0.f, ay = 0.f, az = 0.f, aw = 0.f;

        // Stream this batch's vote slice: warp handles i = w, w+32, ...
#pragma unroll 4
        for (int i = w; i < NI; i += NWARPS) {
            float4 vt = __ldg(&vb[i * NO + lane]);
            float c;
            if (it == 0) {
                c = 1.0f / 32.0f;   // softmax of all-zero logits
            } else {
                // b_ij = sum of agreements with v1 (and v2 at iter 3)
                float bij = vt.x * v1.x + vt.y * v1.y + vt.z * v1.z + vt.w * v1.w;
                if (it == 2)
                    bij += vt.x * v2.x + vt.y * v2.y + vt.z * v2.z + vt.w * v2.w;
                // softmax over o (= over the 32 lanes)
                float m = warpAllMax(bij);
                float e = __expf(bij - m);
                float s = warpAllSum(e);
                c = e / s;
            }
            ax = fmaf(c, vt.x, ax);
            ay = fmaf(c, vt.y, ay);
            az = fmaf(c, vt.z, az);
            aw = fmaf(c, vt.w, aw);
        }

        part4[w][lane] = make_float4(ax, ay, az, aw);
        __syncthreads();

        // Reduce the 32 warp-partials: 128 threads, one per (o,p)
        if (tid < NO * NP) {
            const float* pf = (const float*)part4;
            float s = 0.f;
#pragma unroll
            for (int ww = 0; ww < NWARPS; ++ww)
                s += pf[ww * (NO * NP) + tid];
            s_sh[tid] = s;
        }
        __syncthreads();

        // Squash per output capsule (32 threads)
        if (tid < NO) {
            float sx = s_sh[tid * 4 + 0];
            float sy = s_sh[tid * 4 + 1];
            float sz = s_sh[tid * 4 + 2];
            float sw = s_sh[tid * 4 + 3];
            float n2 = sx * sx + sy * sy + sz * sz + sw * sw + EPSF;
            // v = (n2/(1+n2)) * s/sqrt(n2)  ==  s * sqrt(n2)/(1+n2)
            float f  = sqrtf(n2) / (1.0f + n2);
            float vx = sx * f, vy = sy * f, vz = sz * f, vw = sw * f;
            if (it < 2) {
                vsh4[it][tid] = make_float4(vx, vy, vz, vw);
            } else {
                // final outputs: poses then activations
                float* po = out + ((size_t)b * NO + tid) * NP;
                po[0] = vx; po[1] = vy; po[2] = vz; po[3] = vw;
                float a2 = vx * vx + vy * vy + vz * vz + vw * vw + EPSF;
                out[(size_t)NB * NO * NP + (size_t)b * NO + tid] = sqrtf(a2);
            }
        }
        __syncthreads();

        if (it == 0) v1 = vsh4[0][lane];
        else if (it == 1) v2 = vsh4[1][lane];
    }
}

extern "C" void kernel_launch(void* const* d_in, const int* in_sizes, int n_in,
                              void* d_out, int out_size) {
    const float4* votes = (const float4*)d_in[0];   // [B, I, O, P] fp32, 16B-aligned
    // d_in[1] = activations_in — unused by the reference computation
    float* out = (float*)d_out;
    routing_kernel<<<NB, NTHREADS>>>(votes, out);
}

// round 4
// speedup vs baseline: 1.5870x; 1.5870x over previous
#include <cuda_runtime.h>

// DynamicRouting: B=128, IN=2048, OUT=32, POSE=4, 3 routing iterations.
// poses_out [B,32,4] followed by activations_out [B,32] in d_out.

#define NB 128
#define NI 2048
#define NO 32
#define NP 4
#define EPSF 1e-7f
#define NWARPS 32
#define NTHREADS (NWARPS * 32)
// First NI_EL i's per batch are loaded with an L2::evict_last policy
// (112 MB chip-wide, fits the ~126 MB L2); the tail streams normally.
#define NI_EL 1792

typedef unsigned long long u64;

__device__ __forceinline__ float warpAllSum(float x) {
#pragma unroll
    for (int m = 16; m > 0; m >>= 1)
        x += __shfl_xor_sync(0xffffffffu, x, m);
    return x;
}

// ld.global.nc.v4.f32 with an L2 cache-hint policy (evict_last).
__device__ __forceinline__ float4 ldg_hint(const float4* p, u64 policy) {
    float4 v;
    asm("ld.global.nc.L2::cache_hint.v4.f32 {%0,%1,%2,%3}, [%4], %5;"
        : "=f"(v.x), "=f"(v.y), "=f"(v.z), "=f"(v.w)
        : "l"(p), "l"(policy));
    return v;
}

__global__ __launch_bounds__(NTHREADS, 1)
void routing_kernel(const float4* __restrict__ votes, float* __restrict__ out) {
    const int b    = blockIdx.x;
    const int tid  = threadIdx.x;
    const int w    = tid >> 5;      // warp id, 0..31
    const int lane = tid & 31;      // lane == output-capsule index o

    __shared__ float4 part4[NWARPS][NO];   // per-warp partial s: 16 KB
    __shared__ float4 vsh4[2][NO];         // v1, v2
    __shared__ float  s_sh[NO * NP];       // reduced s

    u64 pol_el;
    asm("createpolicy.fractional.L2::evict_last.b64 %0, 1.0;" : "=l"(pol_el));

    const float4* vb = votes + (size_t)b * (NI * NO);

    float4 v1 = make_float4(0.f, 0.f, 0.f, 0.f);
    float4 v2 = make_float4(0.f, 0.f, 0.f, 0.f);

#pragma unroll
    for (int it = 0; it < 3; ++it) {
        float ax = 0.f, ay = 0.f, az = 0.f, aw = 0.f;

        // ---- main body: i in [0, NI_EL), loads tagged L2 evict_last ----
#pragma unroll 8
        for (int i = w; i < NI_EL; i += NWARPS) {
            float4 vt = ldg_hint(&vb[i * NO + lane], pol_el);
            float c;
            if (it == 0) {
                c = 1.0f / 32.0f;   // softmax of all-zero logits
            } else {
                float bij = vt.x * v1.x + vt.y * v1.y + vt.z * v1.z + vt.w * v1.w;
                if (it == 2)
                    bij += vt.x * v2.x + vt.y * v2.y + vt.z * v2.z + vt.w * v2.w;
                // softmax over the 32 lanes; logits bounded (|b|<~5): no max shift
                float e = __expf(bij);
                float s = warpAllSum(e);
                c = __fdividef(e, s);
            }
            ax = fmaf(c, vt.x, ax);
            ay = fmaf(c, vt.y, ay);
            az = fmaf(c, vt.z, az);
            aw = fmaf(c, vt.w, aw);
        }

        // ---- tail: i in [NI_EL, NI), plain streaming loads ----
#pragma unroll 4
        for (int i = NI_EL + w; i < NI; i += NWARPS) {
            float4 vt = __ldg(&vb[i * NO + lane]);
            float c;
            if (it == 0) {
                c = 1.0f / 32.0f;
            } else {
                float bij = vt.x * v1.x + vt.y * v1.y + vt.z * v1.z + vt.w * v1.w;
                if (it == 2)
                    bij += vt.x * v2.x + vt.y * v2.y + vt.z * v2.z + vt.w * v2.w;
                float e = __expf(bij);
                float s = warpAllSum(e);
                c = __fdividef(e, s);
            }
            ax = fmaf(c, vt.x, ax);
            ay = fmaf(c, vt.y, ay);
            az = fmaf(c, vt.z, az);
            aw = fmaf(c, vt.w, aw);
        }

        part4[w][lane] = make_float4(ax, ay, az, aw);
        __syncthreads();

        // Reduce the 32 warp-partials: 128 threads, one per (o,p)
        if (tid < NO * NP) {
            const float* pf = (const float*)part4;
            float s = 0.f;
#pragma unroll
            for (int ww = 0; ww < NWARPS; ++ww)
                s += pf[ww * (NO * NP) + tid];
            s_sh[tid] = s;
        }
        __syncthreads();

        // Squash per output capsule (32 threads)
        if (tid < NO) {
            float sx = s_sh[tid * 4 + 0];
            float sy = s_sh[tid * 4 + 1];
            float sz = s_sh[tid * 4 + 2];
            float sw = s_sh[tid * 4 + 3];
            float n2 = sx * sx + sy * sy + sz * sz + sw * sw + EPSF;
            // v = (n2/(1+n2)) * s/sqrt(n2)  ==  s * sqrt(n2)/(1+n2)
            float f  = sqrtf(n2) / (1.0f + n2);
            float vx = sx * f, vy = sy * f, vz = sz * f, vw = sw * f;
            if (it < 2) {
                vsh4[it][tid] = make_float4(vx, vy, vz, vw);
            } else {
                float* po = out + ((size_t)b * NO + tid) * NP;
                po[0] = vx; po[1] = vy; po[2] = vz; po[3] = vw;
                float a2 = vx * vx + vy * vy + vz * vz + vw * vw + EPSF;
                out[(size_t)NB * NO * NP + (size_t)b * NO + tid] = sqrtf(a2);
            }
        }
        __syncthreads();

        if (it == 0) v1 = vsh4[0][lane];
        else if (it == 1) v2 = vsh4[1][lane];
    }
}

extern "C" void kernel_launch(void* const* d_in, const int* in_sizes, int n_in,
                              void* d_out, int out_size) {
    const float4* votes = (const float4*)d_in[0];   // [B, I, O, P] fp32, 16B-aligned
    // d_in[1] = activations_in — unused by the reference computation
    float* out = (float*)d_out;
    routing_kernel<<<NB, NTHREADS>>>(votes, out);
}

// round 6
// speedup vs baseline: 2.0865x; 1.3148x over previous
#include <cuda_runtime.h>
#include <cuda_fp16.h>

// DynamicRouting: B=128, IN=2048, OUT=32, POSE=4, 3 routing iterations.
// poses_out [B,32,4] followed by activations_out [B,32] in d_out.
//
// Pass 0 reads fp32 votes (streaming) and writes an fp16 copy into a 64 MB
// __device__ scratch; passes 1-2 read the fp16 copy, which fits L2 (126 MB)
// with slack, so they run at L2 bandwidth instead of DRAM.

#define NB 128
#define NI 2048
#define NO 32
#define NP 4
#define EPSF 1e-7f
#define NWARPS 32
#define NTHREADS (NWARPS * 32)

typedef unsigned long long u64;
typedef unsigned int u32;

// 64 MB fp16 vote cache, same [B,I,O,P] layout. Thread-private RAW (each
// thread re-reads exactly the elements it wrote), phases separated by
// __syncthreads, so no fences needed.
__device__ __align__(16) __half vcache[(size_t)NB * NI * NO * NP];

__device__ __forceinline__ u32 h2_to_u32(__half2 h) {
    union { __half2 h; u32 u; } cvt; cvt.h = h; return cvt.u;
}
__device__ __forceinline__ __half2 u32_to_h2(u32 u) {
    union { u32 u; __half2 h; } cvt; cvt.u = u; return cvt.h;
}

__device__ __forceinline__ float warpAllSum(float x) {
#pragma unroll
    for (int m = 16; m > 0; m >>= 1)
        x += __shfl_xor_sync(0xffffffffu, x, m);
    return x;
}

// fp32 vote load: read-only, streaming (evict_first).
__device__ __forceinline__ float4 ldg_stream(const float4* p, u64 pol) {
    float4 v;
    asm("ld.global.nc.L2::cache_hint.v4.f32 {%0,%1,%2,%3}, [%4], %5;"
        : "=f"(v.x), "=f"(v.y), "=f"(v.z), "=f"(v.w)
        : "l"(p), "l"(pol));
    return v;
}

// fp16 scratch store / load (8 bytes = 4 halves), evict_last.
__device__ __forceinline__ void st_cache(__half* p, u32 a, u32 b, u64 pol) {
    asm volatile("st.global.L2::cache_hint.v2.b32 [%0], {%1,%2}, %3;"
                 :: "l"(p), "r"(a), "r"(b), "l"(pol) : "memory");
}
__device__ __forceinline__ uint2 ld_cache(const __half* p, u64 pol) {
    uint2 r;
    asm("ld.global.L2::cache_hint.v2.b32 {%0,%1}, [%2], %3;"
        : "=r"(r.x), "=r"(r.y) : "l"(p), "l"(pol));
    return r;
}

__global__ __launch_bounds__(NTHREADS, 1)
void routing_kernel(const float4* __restrict__ votes, float* __restrict__ out) {
    const int b    = blockIdx.x;
    const int tid  = threadIdx.x;
    const int w    = tid >> 5;      // warp id, 0..31
    const int lane = tid & 31;      // lane == output-capsule index o

    __shared__ float4 part4[NWARPS][NO];   // per-warp partial s: 16 KB
    __shared__ float4 vsh4[2][NO];         // v1, v2
    __shared__ float  s_sh[NO * NP];       // reduced s

    u64 pol_first, pol_last;
    asm("createpolicy.fractional.L2::evict_first.b64 %0, 1.0;" : "=l"(pol_first));
    asm("createpolicy.fractional.L2::evict_last.b64 %0, 1.0;"  : "=l"(pol_last));

    const float4* vb = votes + (size_t)b * (NI * NO);
    __half*       cb = vcache + (size_t)b * (NI * NO * NP);

    float4 v1 = make_float4(0.f, 0.f, 0.f, 0.f);
    float4 v2 = make_float4(0.f, 0.f, 0.f, 0.f);

#pragma unroll
    for (int it = 0; it < 3; ++it) {
        float ax = 0.f, ay = 0.f, az = 0.f, aw = 0.f;

        if (it == 0) {
            // fp32 streaming pass; uniform c = 1/32; also write fp16 cache.
#pragma unroll 8
            for (int i = w; i < NI; i += NWARPS) {
                float4 vt = ldg_stream(&vb[i * NO + lane], pol_first);
                __half2 h01 = __floats2half2_rn(vt.x, vt.y);
                __half2 h23 = __floats2half2_rn(vt.z, vt.w);
                st_cache(cb + (size_t)(i * NO + lane) * NP,
                         h2_to_u32(h01), h2_to_u32(h23), pol_last);
                ax += vt.x; ay += vt.y; az += vt.z; aw += vt.w;
            }
            ax *= (1.0f / 32.0f); ay *= (1.0f / 32.0f);
            az *= (1.0f / 32.0f); aw *= (1.0f / 32.0f);
        } else {
            // fp16 L2-resident pass.
#pragma unroll 8
            for (int i = w; i < NI; i += NWARPS) {
                uint2 r = ld_cache(cb + (size_t)(i * NO + lane) * NP, pol_last);
                float2 f01 = __half22float2(u32_to_h2(r.x));
                float2 f23 = __half22float2(u32_to_h2(r.y));
                float bij = f01.x * v1.x + f01.y * v1.y + f23.x * v1.z + f23.y * v1.w;
                if (it == 2)
                    bij += f01.x * v2.x + f01.y * v2.y + f23.x * v2.z + f23.y * v2.w;
                // softmax over the 32 lanes; logits bounded (|b|<~5): no max shift
                float e = __expf(bij);
                float s = warpAllSum(e);
                float c = __fdividef(e, s);
                ax = fmaf(c, f01.x, ax);
                ay = fmaf(c, f01.y, ay);
                az = fmaf(c, f23.x, az);
                aw = fmaf(c, f23.y, aw);
            }
        }

        part4[w][lane] = make_float4(ax, ay, az, aw);
        __syncthreads();

        // Reduce the 32 warp-partials: 128 threads, one per (o,p)
        if (tid < NO * NP) {
            const float* pf = (const float*)part4;
            float s = 0.f;
#pragma unroll
            for (int ww = 0; ww < NWARPS; ++ww)
                s += pf[ww * (NO * NP) + tid];
            s_sh[tid] = s;
        }
        __syncthreads();

        // Squash per output capsule (32 threads)
        if (tid < NO) {
            float sx = s_sh[tid * 4 + 0];
            float sy = s_sh[tid * 4 + 1];
            float sz = s_sh[tid * 4 + 2];
            float sw = s_sh[tid * 4 + 3];
            float n2 = sx * sx + sy * sy + sz * sz + sw * sw + EPSF;
            // v = (n2/(1+n2)) * s/sqrt(n2)  ==  s * sqrt(n2)/(1+n2)
            float f  = sqrtf(n2) / (1.0f + n2);
            float vx = sx * f, vy = sy * f, vz = sz * f, vw = sw * f;
            if (it < 2) {
                vsh4[it][tid] = make_float4(vx, vy, vz, vw);
            } else {
                float* po = out + ((size_t)b * NO + tid) * NP;
                po[0] = vx; po[1] = vy; po[2] = vz; po[3] = vw;
                float a2 = vx * vx + vy * vy + vz * vz + vw * vw + EPSF;
                out[(size_t)NB * NO * NP + (size_t)b * NO + tid] = sqrtf(a2);
            }
        }
        __syncthreads();

        if (it == 0) v1 = vsh4[0][lane];
        else if (it == 1) v2 = vsh4[1][lane];
    }
}

extern "C" void kernel_launch(void* const* d_in, const int* in_sizes, int n_in,
                              void* d_out, int out_size) {
    const float4* votes = (const float4*)d_in[0];   // [B, I, O, P] fp32, 16B-aligned
    // d_in[1] = activations_in — unused by the reference computation
    float* out = (float*)d_out;
    routing_kernel<<<NB, NTHREADS>>>(votes, out);
}

// round 7
// speedup vs baseline: 2.3377x; 1.1204x over previous
#include <cuda_runtime.h>
#include <cuda_fp16.h>

// DynamicRouting: B=128, IN=2048, OUT=32, POSE=4, 3 routing iterations.
// poses_out [B,32,4] followed by activations_out [B,32] in d_out.
//
// Pass 0 reads fp32 votes (streaming, evict_first) and writes an fp16 copy
// into a 64 MB __device__ scratch (evict_last, stays L2-resident).
// Scratch layout pairs the two i's a thread owns ((i, i+32)) into one 16-byte
// slot so passes 1-2 read one LDG.128 per 2 votes.
// Softmax over the 32 lanes uses REDUX.SUM on a 2^10 fixed-point exp instead
// of a 5-deep SHFL butterfly.

#define NB 128
#define NI 2048
#define NO 32
#define NP 4
#define EPSF 1e-7f
#define NWARPS 32
#define NTHREADS (NWARPS * 32)
#define NPAIR 32            // pairs per thread: i = w + 64k and w + 64k + 32

typedef unsigned long long u64;
typedef unsigned int u32;

// 64 MB fp16 vote cache. Thread-private RAW (each thread re-reads exactly the
// slots it wrote), phases separated by __syncthreads, so no fences needed.
__device__ __align__(16) __half vcache[(size_t)NB * NI * NO * NP];

__device__ __forceinline__ u32 h2_to_u32(__half2 h) {
    union { __half2 h; u32 u; } cvt; cvt.h = h; return cvt.u;
}
__device__ __forceinline__ __half2 u32_to_h2(u32 u) {
    union { u32 u; __half2 h; } cvt; cvt.u = u; return cvt.h;
}

// fp32 vote load: read-only, streaming (evict_first).
__device__ __forceinline__ float4 ldg_stream(const float4* p, u64 pol) {
    float4 v;
    asm("ld.global.nc.L2::cache_hint.v4.f32 {%0,%1,%2,%3}, [%4], %5;"
        : "=f"(v.x), "=f"(v.y), "=f"(v.z), "=f"(v.w)
        : "l"(p), "l"(pol));
    return v;
}
// 16-byte scratch store / load with evict_last policy.
__device__ __forceinline__ void st_cache4(__half* p, uint4 v, u64 pol) {
    asm volatile("st.global.L2::cache_hint.v4.b32 [%0], {%1,%2,%3,%4}, %5;"
                 :: "l"(p), "r"(v.x), "r"(v.y), "r"(v.z), "r"(v.w), "l"(pol)
                 : "memory");
}
__device__ __forceinline__ uint4 ld_cache4(const __half* p, u64 pol) {
    uint4 r;
    asm("ld.global.L2::cache_hint.v4.b32 {%0,%1,%2,%3}, [%4], %5;"
        : "=r"(r.x), "=r"(r.y), "=r"(r.z), "=r"(r.w) : "l"(p), "l"(pol));
    return r;
}

__global__ __launch_bounds__(NTHREADS, 1)
void routing_kernel(const float4* __restrict__ votes, float* __restrict__ out) {
    const int b    = blockIdx.x;
    const int tid  = threadIdx.x;
    const int w    = tid >> 5;      // warp id, 0..31
    const int lane = tid & 31;      // lane == output-capsule index o

    __shared__ float4 part4[NWARPS][NO];   // per-warp partial s: 16 KB
    __shared__ float4 vsh4[2][NO];         // v1, v2
    __shared__ float  s_sh[NO * NP];       // reduced s

    u64 pol_first, pol_last;
    asm("createpolicy.fractional.L2::evict_first.b64 %0, 1.0;" : "=l"(pol_first));
    asm("createpolicy.fractional.L2::evict_last.b64 %0, 1.0;"  : "=l"(pol_last));

    const float4* vb = votes + (size_t)b * (NI * NO);
    // Per-thread scratch slots: slot(k) holds votes for i0=w+64k and i1=i0+32.
    __half* cb = vcache + (size_t)b * (NI * NO * NP)
                        + ((size_t)(w * NPAIR) * NO + lane) * (2 * NP);

    float4 v1 = make_float4(0.f, 0.f, 0.f, 0.f);
    float4 v2 = make_float4(0.f, 0.f, 0.f, 0.f);

#pragma unroll
    for (int it = 0; it < 3; ++it) {
        float ax = 0.f, ay = 0.f, az = 0.f, aw = 0.f;

        if (it == 0) {
            // fp32 streaming pass; uniform c = 1/32; also write fp16 cache.
#pragma unroll 4
            for (int k = 0; k < NPAIR; ++k) {
                const int i0 = w + 64 * k;
                float4 va = ldg_stream(&vb[i0 * NO + lane], pol_first);
                float4 vc = ldg_stream(&vb[(i0 + 32) * NO + lane], pol_first);
                uint4 pk;
                pk.x = h2_to_u32(__floats2half2_rn(va.x, va.y));
                pk.y = h2_to_u32(__floats2half2_rn(va.z, va.w));
                pk.z = h2_to_u32(__floats2half2_rn(vc.x, vc.y));
                pk.w = h2_to_u32(__floats2half2_rn(vc.z, vc.w));
                st_cache4(cb + (size_t)k * (NO * 2 * NP), pk, pol_last);
                ax += va.x + vc.x; ay += va.y + vc.y;
                az += va.z + vc.z; aw += va.w + vc.w;
            }
            ax *= (1.0f / 32.0f); ay *= (1.0f / 32.0f);
            az *= (1.0f / 32.0f); aw *= (1.0f / 32.0f);
        } else {
            // Logit vector: it==1 -> v1;  it==2 -> v1+v2 (b accumulates).
            float4 wv;
            if (it == 1) wv = v1;
            else wv = make_float4(v1.x + v2.x, v1.y + v2.y,
                                  v1.z + v2.z, v1.w + v2.w);
#pragma unroll 4
            for (int k = 0; k < NPAIR; ++k) {
                uint4 pk = ld_cache4(cb + (size_t)k * (NO * 2 * NP), pol_last);
#pragma unroll
                for (int h = 0; h < 2; ++h) {
                    float2 f01 = __half22float2(u32_to_h2(h ? pk.z : pk.x));
                    float2 f23 = __half22float2(u32_to_h2(h ? pk.w : pk.y));
                    float bij = f01.x * wv.x + f01.y * wv.y
                              + f23.x * wv.z + f23.y * wv.w;
                    // e * 2^10, fixed-point warp sum via REDUX.
                    float ef = exp2f(fmaf(bij, 1.44269504f, 10.0f));
                    u32   u  = __float2uint_rn(ef);
                    u32   s  = __reduce_add_sync(0xffffffffu, u);
                    float sf = fmaxf(__uint2float_rn(s), 1.0f);
                    float c  = __fdividef(ef, sf);   // 2^10 scale cancels
                    ax = fmaf(c, f01.x, ax);
                    ay = fmaf(c, f01.y, ay);
                    az = fmaf(c, f23.x, az);
                    aw = fmaf(c, f23.y, aw);
                }
            }
        }

        part4[w][lane] = make_float4(ax, ay, az, aw);
        __syncthreads();

        // Reduce the 32 warp-partials: 128 threads, one per (o,p)
        if (tid < NO * NP) {
            const float* pf = (const float*)part4;
            float s = 0.f;
#pragma unroll
            for (int ww = 0; ww < NWARPS; ++ww)
                s += pf[ww * (NO * NP) + tid];
            s_sh[tid] = s;
        }
        __syncthreads();

        // Squash per output capsule (32 threads)
        if (tid < NO) {
            float sx = s_sh[tid * 4 + 0];
            float sy = s_sh[tid * 4 + 1];
            float sz = s_sh[tid * 4 + 2];
            float sw = s_sh[tid * 4 + 3];
            float n2 = sx * sx + sy * sy + sz * sz + sw * sw + EPSF;
            // v = (n2/(1+n2)) * s/sqrt(n2)  ==  s * sqrt(n2)/(1+n2)
            float f  = sqrtf(n2) / (1.0f + n2);
            float vx = sx * f, vy = sy * f, vz = sz * f, vw = sw * f;
            if (it < 2) {
                vsh4[it][tid] = make_float4(vx, vy, vz, vw);
            } else {
                float* po = out + ((size_t)b * NO + tid) * NP;
                po[0] = vx; po[1] = vy; po[2] = vz; po[3] = vw;
                float a2 = vx * vx + vy * vy + vz * vz + vw * vw + EPSF;
                out[(size_t)NB * NO * NP + (size_t)b * NO + tid] = sqrtf(a2);
            }
        }
        __syncthreads();

        if (it == 0) v1 = vsh4[0][lane];
        else if (it == 1) v2 = vsh4[1][lane];
    }
}

extern "C" void kernel_launch(void* const* d_in, const int* in_sizes, int n_in,
                              void* d_out, int out_size) {
    const float4* votes = (const float4*)d_in[0];   // [B, I, O, P] fp32, 16B-aligned
    // d_in[1] = activations_in — unused by the reference computation
    float* out = (float*)d_out;
    routing_kernel<<<NB, NTHREADS>>>(votes, out);
}

// round 9
// speedup vs baseline: 2.4179x; 1.0343x over previous
#include <cuda_runtime.h>
#include <cuda_fp16.h>

// DynamicRouting: B=128, IN=2048, OUT=32, POSE=4, 3 routing iterations.
// poses_out [B,32,4] followed by activations_out [B,32] in d_out.
//
// Pass 0 reads fp32 votes (streaming, evict_first) and writes an fp16 copy
// into a 64 MB __device__ scratch (evict_last -> L2-resident for passes 1-2).
// Scratch packs 4 votes (i, i+32, i+64, i+96) per 32-byte slot so the hot
// passes read one LDG.256 per 4 votes. Softmax over the 32 lanes uses
// integer REDUX.SUM on a 2^10 fixed-point exp (fp32 redux doesn't exist on
// sm_103a).

#define NB 128
#define NI 2048
#define NO 32
#define NP 4
#define EPSF 1e-7f
#define NWARPS 32
#define NTHREADS (NWARPS * 32)
#define NQUAD 16            // quads per thread: i = w + 32*(4q+h), h=0..3

typedef unsigned long long u64;
typedef unsigned int u32;

// 64 MB fp16 vote cache, 32B-slot layout (see addr math below). Thread-private
// RAW (each thread re-reads exactly the slots it wrote), phases separated by
// __syncthreads.
__device__ __align__(32) __half vcache[(size_t)NB * NI * NO * NP];

__device__ __forceinline__ u32 h2_to_u32(__half2 h) {
    union { __half2 h; u32 u; } cvt; cvt.h = h; return cvt.u;
}
__device__ __forceinline__ __half2 u32_to_h2(u32 u) {
    union { u32 u; __half2 h; } cvt; cvt.u = u; return cvt.h;
}

__device__ __forceinline__ float ex2_fast(float x) {
    float r;
    asm("ex2.approx.ftz.f32 %0, %1;" : "=f"(r) : "f"(x));
    return r;
}

// fp32 vote load: read-only, streaming (evict_first).
__device__ __forceinline__ float4 ldg_stream(const float4* p, u64 pol) {
    float4 v;
    asm("ld.global.nc.L2::cache_hint.v4.f32 {%0,%1,%2,%3}, [%4], %5;"
        : "=f"(v.x), "=f"(v.y), "=f"(v.z), "=f"(v.w)
        : "l"(p), "l"(pol));
    return v;
}
// 16-byte scratch store with evict_last policy.
__device__ __forceinline__ void st_cache4(__half* p, u32 a, u32 b, u32 c, u32 d, u64 pol) {
    asm volatile("st.global.L2::cache_hint.v4.b32 [%0], {%1,%2,%3,%4}, %5;"
                 :: "l"(p), "r"(a), "r"(b), "r"(c), "r"(d), "l"(pol)
                 : "memory");
}
// 32-byte scratch load (LDG.256), evict_last.
__device__ __forceinline__ void ld_cache8(const __half* p, u32* r) {
    asm("ld.global.nc.L2::evict_last.v8.b32 {%0,%1,%2,%3,%4,%5,%6,%7}, [%8];"
        : "=r"(r[0]), "=r"(r[1]), "=r"(r[2]), "=r"(r[3]),
          "=r"(r[4]), "=r"(r[5]), "=r"(r[6]), "=r"(r[7])
        : "l"(p));
}

__global__ __launch_bounds__(NTHREADS, 1)
void routing_kernel(const float4* __restrict__ votes, float* __restrict__ out) {
    const int b    = blockIdx.x;
    const int tid  = threadIdx.x;
    const int w    = tid >> 5;      // warp id, 0..31
    const int lane = tid & 31;      // lane == output-capsule index o

    __shared__ float4 part4[NWARPS][NO];   // per-warp partial s: 16 KB
    __shared__ float4 vsh4[2][NO];         // v1, v2
    __shared__ float  s_sh[NO * NP];       // reduced s

    u64 pol_first, pol_last;
    asm("createpolicy.fractional.L2::evict_first.b64 %0, 1.0;" : "=l"(pol_first));
    asm("createpolicy.fractional.L2::evict_last.b64 %0, 1.0;"  : "=l"(pol_last));

    const float4* vb = votes + (size_t)b * (NI * NO);
    // Thread's scratch: slot(q) at cbase + ((w*NQUAD+q)*32 + lane)*16 halves.
    __half* cbase = vcache + (size_t)b * (NI * NO * NP);
    __half* ct    = cbase + ((size_t)(w * NQUAD) * 32 + lane) * 16;
    // stride between consecutive q for this thread: 32 lanes * 16 halves = 512.

    float4 v1 = make_float4(0.f, 0.f, 0.f, 0.f);
    float4 v2 = make_float4(0.f, 0.f, 0.f, 0.f);

#pragma unroll
    for (int it = 0; it < 3; ++it) {
        float ax = 0.f, ay = 0.f, az = 0.f, aw = 0.f;

        if (it == 0) {
            // fp32 streaming pass; uniform c = 1/32; also write fp16 cache.
#pragma unroll 2
            for (int q = 0; q < NQUAD; ++q) {
                u32 pk[8];
#pragma unroll
                for (int h = 0; h < 4; ++h) {
                    const int i = w + 32 * (4 * q + h);
                    float4 vt = ldg_stream(&vb[i * NO + lane], pol_first);
                    pk[2 * h + 0] = h2_to_u32(__floats2half2_rn(vt.x, vt.y));
                    pk[2 * h + 1] = h2_to_u32(__floats2half2_rn(vt.z, vt.w));
                    ax += vt.x; ay += vt.y; az += vt.z; aw += vt.w;
                }
                __half* sp = ct + (size_t)q * 512;
                st_cache4(sp,     pk[0], pk[1], pk[2], pk[3], pol_last);
                st_cache4(sp + 8, pk[4], pk[5], pk[6], pk[7], pol_last);
            }
            ax *= (1.0f / 32.0f); ay *= (1.0f / 32.0f);
            az *= (1.0f / 32.0f); aw *= (1.0f / 32.0f);
        } else {
            // Logit vector: it==1 -> v1;  it==2 -> v1+v2 (b accumulates).
            float4 wv;
            if (it == 1) wv = v1;
            else wv = make_float4(v1.x + v2.x, v1.y + v2.y,
                                  v1.z + v2.z, v1.w + v2.w);
            const float l2e = 1.44269504f;
#pragma unroll 2
            for (int q = 0; q < NQUAD; ++q) {
                u32 pk[8];
                ld_cache8(ct + (size_t)q * 512, pk);
#pragma unroll
                for (int h = 0; h < 4; ++h) {
                    float2 f01 = __half22float2(u32_to_h2(pk[2 * h + 0]));
                    float2 f23 = __half22float2(u32_to_h2(pk[2 * h + 1]));
                    float bij = f01.x * wv.x + f01.y * wv.y
                              + f23.x * wv.z + f23.y * wv.w;
                    // e^bij * 2^10, fixed-point warp sum via integer REDUX.
                    float ef = ex2_fast(fmaf(bij, l2e, 10.0f));
                    u32   u  = __float2uint_rn(ef);
                    u32   s  = __reduce_add_sync(0xffffffffu, u);
                    float sf = fmaxf(__uint2float_rn(s), 1.0f);
                    float c  = __fdividef(ef, sf);   // 2^10 scale cancels
                    ax = fmaf(c, f01.x, ax);
                    ay = fmaf(c, f01.y, ay);
                    az = fmaf(c, f23.x, az);
                    aw = fmaf(c, f23.y, aw);
                }
            }
        }

        part4[w][lane] = make_float4(ax, ay, az, aw);
        __syncthreads();

        // Reduce the 32 warp-partials: 128 threads, one per (o,p)
        if (tid < NO * NP) {
            const float* pf = (const float*)part4;
            float s = 0.f;
#pragma unroll
            for (int ww = 0; ww < NWARPS; ++ww)
                s += pf[ww * (NO * NP) + tid];
            s_sh[tid] = s;
        }
        __syncthreads();

        // Squash per output capsule (32 threads)
        if (tid < NO) {
            float sx = s_sh[tid * 4 + 0];
            float sy = s_sh[tid * 4 + 1];
            float sz = s_sh[tid * 4 + 2];
            float sw = s_sh[tid * 4 + 3];
            float n2 = sx * sx + sy * sy + sz * sz + sw * sw + EPSF;
            // v = (n2/(1+n2)) * s/sqrt(n2)  ==  s * sqrt(n2)/(1+n2)
            float f  = sqrtf(n2) / (1.0f + n2);
            float vx = sx * f, vy = sy * f, vz = sz * f, vw = sw * f;
            if (it < 2) {
                vsh4[it][tid] = make_float4(vx, vy, vz, vw);
            } else {
                float* po = out + ((size_t)b * NO + tid) * NP;
                po[0] = vx; po[1] = vy; po[2] = vz; po[3] = vw;
                float a2 = vx * vx + vy * vy + vz * vz + vw * vw + EPSF;
                out[(size_t)NB * NO * NP + (size_t)b * NO + tid] = sqrtf(a2);
            }
        }
        __syncthreads();

        if (it == 0) v1 = vsh4[0][lane];
        else if (it == 1) v2 = vsh4[1][lane];
    }
}

extern "C" void kernel_launch(void* const* d_in, const int* in_sizes, int n_in,
                              void* d_out, int out_size) {
    const float4* votes = (const float4*)d_in[0];   // [B, I, O, P] fp32, 16B-aligned
    // d_in[1] = activations_in — unused by the reference computation
    float* out = (float*)d_out;
    routing_kernel<<<NB, NTHREADS>>>(votes, out);
}